// round 1
// baseline (speedup 1.0000x reference)
#include <cuda_runtime.h>
#include <cstdint>

// RSNN block: out = LIF16( x @ W^T + b ) / 16
// x: [M, K] fp32, W: [N, K] fp32, b: [N] fp32, out: [M, N] fp32
// M=32768, N=512, K=512 (derived from in_sizes; assumes divisibility by tiles)

#define BM 128
#define BN 64
#define BK 16
#define TM 8
#define TN 4
#define THREADS 256

// padded strides (in floats) keeping 16B alignment for LDS.128
#define AS_STRIDE (BM + 8)       // 136 -> 544B, %16 == 0
#define BS_STRIDE (2 * BN + 8)   // 136 -> 544B, %16 == 0

typedef unsigned long long ull;

__device__ __forceinline__ void ffma2(ull& d, ull a, ull b) {
    asm("fma.rn.f32x2 %0, %1, %2, %3;" : "=l"(d) : "l"(a), "l"(b), "l"(d));
}

__device__ __forceinline__ void unpack2(ull v, float& lo, float& hi) {
    unsigned int l, h;
    asm("mov.b64 {%0, %1}, %2;" : "=r"(l), "=r"(h) : "l"(v));
    lo = __uint_as_float(l);
    hi = __uint_as_float(h);
}

// 16-step LIF with tau=2, v_th=1, hard reset to 0, matching reference fp ops:
// v = v + (cur - v) * 0.5 ; spike = (v >= 1) ; v = (1-spike)*v ; acc += spike
__device__ __forceinline__ float lif16(float cur) {
    float v = 0.0f;
    float cnt = 0.0f;
#pragma unroll
    for (int t = 0; t < 16; t++) {
        v = fmaf(cur - v, 0.5f, v);
        if (v >= 1.0f) { cnt += 1.0f; v = 0.0f; }
    }
    return cnt * 0.0625f;
}

__global__ __launch_bounds__(THREADS)
void gemm_lif_kernel(const float* __restrict__ X,
                     const float* __restrict__ W,
                     const float* __restrict__ bias,
                     float* __restrict__ out,
                     int M, int N, int K) {
    __shared__ float As[BK][AS_STRIDE];    // [k][m], m-contiguous
    __shared__ float Bs2[BK][BS_STRIDE];   // [k][2n], each W value duplicated (n,n)

    const int tid = threadIdx.x;
    const int tx = tid & 15;   // n-direction, 16 * TN = 64
    const int ty = tid >> 4;   // m-direction, 16 * TM = 128
    const int m0 = blockIdx.y * BM;
    const int n0 = blockIdx.x * BN;

    // accumulators: 4 m-pairs x 4 n, packed f32x2 (lo = even row, hi = odd row)
    ull acc[4][TN];
#pragma unroll
    for (int i = 0; i < 4; i++)
#pragma unroll
        for (int j = 0; j < TN; j++) acc[i][j] = 0ull;

    const int lrow = tid >> 2;          // 0..63
    const int lkq  = (tid & 3) << 2;    // 0,4,8,12

    for (int k0 = 0; k0 < K; k0 += BK) {
        // ---- load A tile: 128 rows x 16 k, transposed into As[k][m] ----
#pragma unroll
        for (int r = 0; r < 2; r++) {
            int row = lrow + r * 64;
            float4 v = *reinterpret_cast<const float4*>(
                X + (size_t)(m0 + row) * K + k0 + lkq);
            As[lkq + 0][row] = v.x;
            As[lkq + 1][row] = v.y;
            As[lkq + 2][row] = v.z;
            As[lkq + 3][row] = v.w;
        }
        // ---- load B tile: 64 rows (n) x 16 k, duplicated into Bs2[k][2n+{0,1}] ----
        {
            int row = lrow;  // 0..63
            float4 v = *reinterpret_cast<const float4*>(
                W + (size_t)(n0 + row) * K + k0 + lkq);
            Bs2[lkq + 0][2 * row] = v.x; Bs2[lkq + 0][2 * row + 1] = v.x;
            Bs2[lkq + 1][2 * row] = v.y; Bs2[lkq + 1][2 * row + 1] = v.y;
            Bs2[lkq + 2][2 * row] = v.z; Bs2[lkq + 2][2 * row + 1] = v.z;
            Bs2[lkq + 3][2 * row] = v.w; Bs2[lkq + 3][2 * row + 1] = v.w;
        }
        __syncthreads();

#pragma unroll
        for (int k = 0; k < BK; k++) {
            // A: 8 consecutive m values -> 4 packed pairs (2x LDS.128)
            union { float4 v; ull u[2]; } A0, A1;
            A0.v = *reinterpret_cast<const float4*>(&As[k][ty * TM]);
            A1.v = *reinterpret_cast<const float4*>(&As[k][ty * TM + 4]);
            ull ap[4] = { A0.u[0], A0.u[1], A1.u[0], A1.u[1] };
            // B: 4 duplicated pairs (b_j, b_j) -> 2x LDS.128
            union { float4 v; ull u[2]; } B0, B1;
            B0.v = *reinterpret_cast<const float4*>(&Bs2[k][tx * TN * 2]);
            B1.v = *reinterpret_cast<const float4*>(&Bs2[k][tx * TN * 2 + 4]);
            ull bp[4] = { B0.u[0], B0.u[1], B1.u[0], B1.u[1] };

#pragma unroll
            for (int i = 0; i < 4; i++)
#pragma unroll
                for (int j = 0; j < TN; j++)
                    ffma2(acc[i][j], ap[i], bp[j]);
        }
        __syncthreads();
    }

    // ---- epilogue: bias + LIF + store (float4 per row) ----
    const float4 bb = *reinterpret_cast<const float4*>(bias + n0 + tx * TN);
    const float bv[4] = { bb.x, bb.y, bb.z, bb.w };

#pragma unroll
    for (int i = 0; i < 4; i++) {
        float lo[4], hi[4];
#pragma unroll
        for (int j = 0; j < TN; j++) unpack2(acc[i][j], lo[j], hi[j]);

        float4 o0, o1;
        o0.x = lif16(lo[0] + bv[0]);
        o0.y = lif16(lo[1] + bv[1]);
        o0.z = lif16(lo[2] + bv[2]);
        o0.w = lif16(lo[3] + bv[3]);
        o1.x = lif16(hi[0] + bv[0]);
        o1.y = lif16(hi[1] + bv[1]);
        o1.z = lif16(hi[2] + bv[2]);
        o1.w = lif16(hi[3] + bv[3]);

        int row0 = m0 + ty * TM + 2 * i;
        float* p0 = out + (size_t)row0 * N + n0 + tx * TN;
        float* p1 = p0 + N;
        *reinterpret_cast<float4*>(p0) = o0;
        *reinterpret_cast<float4*>(p1) = o1;
    }
}

extern "C" void kernel_launch(void* const* d_in, const int* in_sizes, int n_in,
                              void* d_out, int out_size) {
    const float* x = (const float*)d_in[0];
    const float* W = (const float*)d_in[1];
    const float* b = (const float*)d_in[2];
    float* out = (float*)d_out;

    const int N = in_sizes[2];            // 512
    const int K = in_sizes[1] / N;        // 512
    const int M = in_sizes[0] / K;        // 32768

    dim3 grid(N / BN, M / BM);
    gemm_lif_kernel<<<grid, THREADS>>>(x, W, b, out, M, N, K);
}

// round 6
// speedup vs baseline: 1.4524x; 1.4524x over previous
#include <cuda_runtime.h>
#include <cstdint>

// ============================================================
// RSNN: out = LIF16(x @ W^T + b)/16,  M=32768, N=512, K=512 fp32
// Bit-exact fp32 GEMM (strictly k-sequential FMA per output ==
// cuBLAS/reference rounding) on the FFMA2 (fma.rn.f32x2) pipe,
// register-blocked 16x8 per thread to be fma-bound, fused LIF.
// ============================================================

typedef unsigned int u32;
typedef unsigned long long ull;

#define THREADS 256
#define BM 256
#define BN 128
#define BK 16

#define AS_STR 260           // floats per A smem row (k-major) ; 1040 B, %16==0
#define BS_STR 136           // floats per B smem row           ;  544 B, %16==0
#define A_BYTES (BK * AS_STR * 4)          // 16640
#define B_BYTES (BK * BS_STR * 4)          // 8704
#define BUF_BYTES (A_BYTES + B_BYTES)      // 25344
#define SM_TOTAL (2 * BUF_BYTES)           // 50688

__device__ __forceinline__ void ffma2(ull& d, ull a, ull b) {
    asm("fma.rn.f32x2 %0, %1, %2, %3;" : "=l"(d) : "l"(a), "l"(b), "l"(d));
}
__device__ __forceinline__ ull pack_dup(float x) {
    ull r;
    u32 u = __float_as_uint(x);
    asm("mov.b64 %0, {%1, %1};" : "=l"(r) : "r"(u));
    return r;
}
__device__ __forceinline__ void unpack2(ull v, float& lo, float& hi) {
    u32 l, h;
    asm("mov.b64 {%0, %1}, %2;" : "=r"(l), "=r"(h) : "l"(v));
    lo = __uint_as_float(l);
    hi = __uint_as_float(h);
}

// LIF: identical fp ops to reference per step
__device__ __forceinline__ float lif16(float cur) {
    float v = 0.0f, cnt = 0.0f;
#pragma unroll
    for (int t = 0; t < 16; t++) {
        v = fmaf(cur - v, 0.5f, v);
        if (v >= 1.0f) { cnt += 1.0f; v = 0.0f; }
    }
    return cnt * 0.0625f;
}

__global__ void __launch_bounds__(THREADS)
gemm_lif(const float* __restrict__ X, const float* __restrict__ W,
         const float* __restrict__ bias, float* __restrict__ out,
         int M, int N, int K) {
    extern __shared__ char smem[];

    const int tid = threadIdx.x;
    const int tx = tid & 15;          // n: 16 * 8 = 128
    const int ty = tid >> 4;          // m: 16 * 16 = 256
    const int n0 = blockIdx.x * BN;   // n fastest -> A tile L2 reuse across 4 CTAs
    const int m0 = blockIdx.y * BM;

    // accumulators: 8 m-pairs x 8 n  (f32x2: lo=even m, hi=odd m)
    ull acc[8][8];
#pragma unroll
    for (int i = 0; i < 8; i++)
#pragma unroll
        for (int j = 0; j < 8; j++) acc[i][j] = 0ull;

    // ---- loader mapping ----
    const int ar = tid >> 2;          // A: 64 rows per step, 4 steps
    const int as = tid & 3;           // A: k-seg (4 floats)
    const int br = tid & 127;         // B: row
    const int bs = tid >> 7;          // B: k-half (8 floats)

    const float* Ag = X + (size_t)(m0 + ar) * K + 4 * as;
    const float* Bg = W + (size_t)(n0 + br) * K + 8 * bs;

    float4 ra[4], rb[2];
    const int NCHUNK = K / BK;        // 32

    // ---- prolog: load + store chunk 0 ----
#pragma unroll
    for (int i = 0; i < 4; i++)
        ra[i] = *reinterpret_cast<const float4*>(Ag + (size_t)(i * 64) * K);
    rb[0] = *reinterpret_cast<const float4*>(Bg);
    rb[1] = *reinterpret_cast<const float4*>(Bg + 4);
    {
        float* As = reinterpret_cast<float*>(smem);
        float* Bs = reinterpret_cast<float*>(smem + A_BYTES);
#pragma unroll
        for (int i = 0; i < 4; i++) {
            int r = ar + i * 64;
            As[(4 * as + 0) * AS_STR + r] = ra[i].x;
            As[(4 * as + 1) * AS_STR + r] = ra[i].y;
            As[(4 * as + 2) * AS_STR + r] = ra[i].z;
            As[(4 * as + 3) * AS_STR + r] = ra[i].w;
        }
#pragma unroll
        for (int u = 0; u < 2; u++) {
            int kb = 8 * bs + 4 * u;
            Bs[(kb + 0) * BS_STR + br] = rb[u].x;
            Bs[(kb + 1) * BS_STR + br] = rb[u].y;
            Bs[(kb + 2) * BS_STR + br] = rb[u].z;
            Bs[(kb + 3) * BS_STR + br] = rb[u].w;
        }
    }
    __syncthreads();

    for (int c = 0; c < NCHUNK; c++) {
        // ---- global loads for next chunk ----
        if (c + 1 < NCHUNK) {
            const float* Ap = Ag + (c + 1) * BK;
            const float* Bp = Bg + (c + 1) * BK;
#pragma unroll
            for (int i = 0; i < 4; i++)
                ra[i] = *reinterpret_cast<const float4*>(Ap + (size_t)(i * 64) * K);
            rb[0] = *reinterpret_cast<const float4*>(Bp);
            rb[1] = *reinterpret_cast<const float4*>(Bp + 4);
        }

        // ---- compute chunk c ----
        const float* As = reinterpret_cast<const float*>(smem + (c & 1) * BUF_BYTES);
        const float* Bs = reinterpret_cast<const float*>(smem + (c & 1) * BUF_BYTES + A_BYTES);
#pragma unroll
        for (int k = 0; k < BK; k++) {
            const float* arow = As + k * AS_STR + ty * 16;
            union { float4 v; ull u[2]; } a0, a1, a2, a3;
            a0.v = *reinterpret_cast<const float4*>(arow + 0);
            a1.v = *reinterpret_cast<const float4*>(arow + 4);
            a2.v = *reinterpret_cast<const float4*>(arow + 8);
            a3.v = *reinterpret_cast<const float4*>(arow + 12);
            ull ap[8] = { a0.u[0], a0.u[1], a1.u[0], a1.u[1],
                          a2.u[0], a2.u[1], a3.u[0], a3.u[1] };

            const float* brow = Bs + k * BS_STR + tx * 8;
            float4 b0 = *reinterpret_cast<const float4*>(brow);
            float4 b1 = *reinterpret_cast<const float4*>(brow + 4);
            ull bp[8] = { pack_dup(b0.x), pack_dup(b0.y), pack_dup(b0.z), pack_dup(b0.w),
                          pack_dup(b1.x), pack_dup(b1.y), pack_dup(b1.z), pack_dup(b1.w) };

#pragma unroll
            for (int i = 0; i < 8; i++)
#pragma unroll
                for (int j = 0; j < 8; j++)
                    ffma2(acc[i][j], ap[i], bp[j]);
        }

        // ---- store staged regs for next chunk ----
        if (c + 1 < NCHUNK) {
            float* Asw = reinterpret_cast<float*>(smem + ((c + 1) & 1) * BUF_BYTES);
            float* Bsw = reinterpret_cast<float*>(smem + ((c + 1) & 1) * BUF_BYTES + A_BYTES);
#pragma unroll
            for (int i = 0; i < 4; i++) {
                int r = ar + i * 64;
                Asw[(4 * as + 0) * AS_STR + r] = ra[i].x;
                Asw[(4 * as + 1) * AS_STR + r] = ra[i].y;
                Asw[(4 * as + 2) * AS_STR + r] = ra[i].z;
                Asw[(4 * as + 3) * AS_STR + r] = ra[i].w;
            }
#pragma unroll
            for (int u = 0; u < 2; u++) {
                int kb = 8 * bs + 4 * u;
                Bsw[(kb + 0) * BS_STR + br] = rb[u].x;
                Bsw[(kb + 1) * BS_STR + br] = rb[u].y;
                Bsw[(kb + 2) * BS_STR + br] = rb[u].z;
                Bsw[(kb + 3) * BS_STR + br] = rb[u].w;
            }
        }
        __syncthreads();
    }

    // ---- epilogue: bias + LIF + store ----
    float4 bq0 = *reinterpret_cast<const float4*>(bias + n0 + tx * 8);
    float4 bq1 = *reinterpret_cast<const float4*>(bias + n0 + tx * 8 + 4);
    const float bv[8] = { bq0.x, bq0.y, bq0.z, bq0.w, bq1.x, bq1.y, bq1.z, bq1.w };

#pragma unroll
    for (int i = 0; i < 8; i++) {
        float lo[8], hi[8];
#pragma unroll
        for (int j = 0; j < 8; j++) unpack2(acc[i][j], lo[j], hi[j]);

        int m_lo = m0 + ty * 16 + 2 * i;
        float* p0 = out + (size_t)m_lo * N + n0 + tx * 8;
        float* p1 = p0 + N;

        float4 o;
        o.x = lif16(lo[0] + bv[0]); o.y = lif16(lo[1] + bv[1]);
        o.z = lif16(lo[2] + bv[2]); o.w = lif16(lo[3] + bv[3]);
        *reinterpret_cast<float4*>(p0) = o;
        o.x = lif16(lo[4] + bv[4]); o.y = lif16(lo[5] + bv[5]);
        o.z = lif16(lo[6] + bv[6]); o.w = lif16(lo[7] + bv[7]);
        *reinterpret_cast<float4*>(p0 + 4) = o;
        o.x = lif16(hi[0] + bv[0]); o.y = lif16(hi[1] + bv[1]);
        o.z = lif16(hi[2] + bv[2]); o.w = lif16(hi[3] + bv[3]);
        *reinterpret_cast<float4*>(p1) = o;
        o.x = lif16(hi[4] + bv[4]); o.y = lif16(hi[5] + bv[5]);
        o.z = lif16(hi[6] + bv[6]); o.w = lif16(hi[7] + bv[7]);
        *reinterpret_cast<float4*>(p1 + 4) = o;
    }
}

extern "C" void kernel_launch(void* const* d_in, const int* in_sizes, int n_in,
                              void* d_out, int out_size) {
    const float* x = (const float*)d_in[0];
    const float* W = (const float*)d_in[1];
    const float* b = (const float*)d_in[2];
    float* out = (float*)d_out;

    const int N = in_sizes[2];          // 512
    const int K = in_sizes[1] / N;      // 512
    const int M = in_sizes[0] / K;      // 32768

    cudaFuncSetAttribute(gemm_lif, cudaFuncAttributeMaxDynamicSharedMemorySize, SM_TOTAL);
    dim3 grid(N / BN, M / BM);
    gemm_lif<<<grid, THREADS, SM_TOTAL>>>(x, W, b, out, M, N, K);
}